// round 4
// baseline (speedup 1.0000x reference)
#include <cuda_runtime.h>
#include <cstddef>

#define Bq 256
#define Sq 4096
#define Hq 64
#define Cq 32            // chunks along S
#define Lq (Sq / Cq)     // 128 elements per chunk
#define CPB 8            // chunks per k_scan block

// Per-(b,chunk,h) chunk aggregates of omega*delta. 2 MB -> L2-resident.
__device__ __align__(16) float g_part[(size_t)Bq * Cq * Hq];

__device__ __forceinline__ unsigned long long pack2(float lo, float hi) {
    unsigned long long r;
    asm("mov.b64 %0, {%1, %2};" : "=l"(r) : "f"(lo), "f"(hi));
    return r;
}
__device__ __forceinline__ void unpack2(unsigned long long v, float& lo, float& hi) {
    asm("mov.b64 {%0, %1}, %2;" : "=f"(lo), "=f"(hi) : "l"(v));
}
__device__ __forceinline__ unsigned long long fma2(unsigned long long a,
                                                   unsigned long long b,
                                                   unsigned long long c) {
    unsigned long long d;
    asm("fma.rn.f32x2 %0, %1, %2, %3;" : "=l"(d) : "l"(a), "l"(b), "l"(c));
    return d;
}
__device__ __forceinline__ unsigned long long add2(unsigned long long a,
                                                   unsigned long long b) {
    unsigned long long d;
    asm("add.rn.f32x2 %0, %1, %2;" : "=l"(d) : "l"(a), "l"(b));
    return d;
}

#define MAGIC  12582912.0f   // 1.5 * 2^23: (u + MAGIC) - MAGIC == rint(u) for |u| < 2^22

// ---------------- Phase 1: chunk aggregates via separability ----------------
// agg(b,c,h) = om*2pi * ( we2*Sum(x) + L*be2 - Sum_s rint(u_s) ),  u_s = x_s*we2 + be2
__global__ void __launch_bounds__(Hq) k_partials(const float* __restrict__ x,
                                                 const float* __restrict__ W_e,
                                                 const float* __restrict__ b_e,
                                                 const float* __restrict__ omega) {
    __shared__ float2 shx[Lq / 2];
    __shared__ float s_red[2];
    const int bc = blockIdx.x;          // b*Cq + c
    const int h  = threadIdx.x;
    const int b  = bc >> 5;
    const int c  = bc & (Cq - 1);

    const float2* xc = (const float2*)(x + (size_t)b * Sq + (size_t)c * Lq);
    float2 v = __ldg(xc + h);
    shx[h] = v;

    const float INV_2PI = 0.15915494309189535f;
    const float TWO_PI  = 6.283185307179586f;
    const float we2 = W_e[h]   * INV_2PI;
    const float be2 = b_e[h]   * INV_2PI;
    const float om2 = omega[h] * TWO_PI;

    // Cooperative Sum(x) over the chunk.
    float ps = v.x + v.y;
#pragma unroll
    for (int o = 16; o > 0; o >>= 1) ps += __shfl_down_sync(0xffffffffu, ps, o);
    if ((h & 31) == 0) s_red[h >> 5] = ps;
    __syncthreads();
    const float sx = s_red[0] + s_red[1];

    // Sum of rint(u_s) via packed magic rounding: 2 elements per instruction.
    const unsigned long long we2p  = pack2(we2, we2);
    const unsigned long long be2p  = pack2(be2, be2);
    const unsigned long long Mp    = pack2(MAGIC, MAGIC);
    const unsigned long long negMp = pack2(-MAGIC, -MAGIC);
    unsigned long long racc2 = 0ull;   // {0.0f, 0.0f}
#pragma unroll 16
    for (int i = 0; i < Lq / 2; ++i) {
        float2 xv = shx[i];
        unsigned long long u2 = fma2(pack2(xv.x, xv.y), we2p, be2p);
        unsigned long long t2 = add2(u2, Mp);
        unsigned long long k2 = add2(t2, negMp);   // exact: rint values
        racc2 = add2(racc2, k2);
    }
    float rlo, rhi;
    unpack2(racc2, rlo, rhi);
    float agg = om2 * (fmaf(we2, sx, (float)Lq * be2) - (rlo + rhi));
    g_part[(size_t)bc * Hq + h] = agg;
}

// ---------------- Phase 2: fused prefix + scan (float4 stores) + output head ----------------
__global__ void __launch_bounds__(128) k_scan(const float* __restrict__ x,
                                              const float* __restrict__ W_e,
                                              const float* __restrict__ b_e,
                                              const float* __restrict__ omega,
                                              const float* __restrict__ W_r,
                                              const float* __restrict__ b_r,
                                              float* __restrict__ out,
                                              float* __restrict__ hseq) {
    __shared__ float shx[CPB * 132];    // 132-float pitch: no 2-group bank conflicts
    const int t   = threadIdx.x;
    const int bc0 = blockIdx.x * CPB;
    const int b   = bc0 >> 5;
    const int c0  = bc0 & (Cq - 1);

    // Stage 8 contiguous chunks (1024 floats) of this row, coalesced.
    const float4* xg = (const float4*)(x + (size_t)b * Sq + (size_t)c0 * Lq);
#pragma unroll
    for (int i = 0; i < 2; ++i) {
        int idx = t + i * 128;          // float4 index 0..255
        float4 v = __ldg(xg + idx);
        int sg = idx * 4;
        int g = sg >> 7, sl = sg & (Lq - 1);
        *(float4*)&shx[g * 132 + sl] = v;
    }

    const int g  = t >> 4;              // chunk group 0..7
    const int l  = t & 15;
    const int h0 = 4 * l;
    const int c  = c0 + g;

    const float INV_2PI = 0.15915494309189535f;
    const float TWO_PI  = 6.283185307179586f;
    float we[4], be[4], om[4];
#pragma unroll
    for (int j = 0; j < 4; ++j) {
        we[j] = W_e[h0 + j]   * INV_2PI;
        be[j] = b_e[h0 + j]   * INV_2PI;
        om[j] = omega[h0 + j] * TWO_PI;
    }

    // Carry: sum of predecessor chunk aggregates (L2-resident float4 loads).
    float a0 = 0.f, a1 = 0.f, a2 = 0.f, a3 = 0.f;
    const float4* gp = (const float4*)(&g_part[(size_t)(b << 5) * Hq + h0]);
    for (int cc = 0; cc < c; ++cc) {
        float4 v = __ldg(gp + cc * (Hq / 4));
        a0 += v.x; a1 += v.y; a2 += v.z; a3 += v.w;
    }
    __syncthreads();

    // Carry-seeded scan: 4 channels/thread, one float4 streaming store per step.
    const float* xs_p = &shx[g * 132];
    float4* hp = (float4*)(hseq + ((size_t)b * Sq + (size_t)c * Lq) * Hq + h0);
#pragma unroll 8
    for (int s = 0; s < Lq; ++s) {
        float xs = xs_p[s];
        float4 o;
        { float u = fmaf(xs, we[0], be[0]); float tt = u + MAGIC; float k = tt - MAGIC;
          a0 = fmaf(om[0], u - k, a0); o.x = a0; }
        { float u = fmaf(xs, we[1], be[1]); float tt = u + MAGIC; float k = tt - MAGIC;
          a1 = fmaf(om[1], u - k, a1); o.y = a1; }
        { float u = fmaf(xs, we[2], be[2]); float tt = u + MAGIC; float k = tt - MAGIC;
          a2 = fmaf(om[2], u - k, a2); o.z = a2; }
        { float u = fmaf(xs, we[3], be[3]); float tt = u + MAGIC; float k = tt - MAGIC;
          a3 = fmaf(om[3], u - k, a3); o.w = a3; }
        __stcs(hp + s * (Hq / 4), o);
    }

    // Output head: last chunk's final accumulators are ph[b][h0..h0+3].
    if (c == Cq - 1) {
        float ph[4] = {a0, a1, a2, a3};
        float tval = 0.0f;
#pragma unroll
        for (int j = 0; j < 4; ++j) {
            int hh = h0 + j;
            tval = fmaf(ph[j], W_r[2 * Hq + hh], tval);
            tval = fmaf(cosf(ph[j]), W_r[hh], tval);
            tval = fmaf(sinf(ph[j]), W_r[Hq + hh], tval);
        }
        // Reduce across the 16 lanes of this group (upper half of warp 3).
#pragma unroll
        for (int o = 8; o > 0; o >>= 1)
            tval += __shfl_down_sync(0xFFFF0000u, tval, o, 16);
        if (l == 0) out[b] = tval + b_r[0];
    }
}

extern "C" void kernel_launch(void* const* d_in, const int* in_sizes, int n_in,
                              void* d_out, int out_size) {
    const float* x     = (const float*)d_in[0];
    const float* W_e   = (const float*)d_in[1];
    const float* b_e   = (const float*)d_in[2];
    const float* omega = (const float*)d_in[3];
    const float* W_r   = (const float*)d_in[4];
    const float* b_r   = (const float*)d_in[5];

    float* out  = (float*)d_out;        // out = B floats
    float* hseq = (float*)d_out + Bq;   // then Hseq = B*S*H floats

    k_partials<<<Bq * Cq, Hq>>>(x, W_e, b_e, omega);
    k_scan<<<(Bq * Cq) / CPB, 128>>>(x, W_e, b_e, omega, W_r, b_r, out, hseq);
}

// round 5
// speedup vs baseline: 1.0973x; 1.0973x over previous
#include <cuda_runtime.h>
#include <cstddef>

#define Bq 256
#define Sq 4096
#define Hq 64
#define Cq 32            // chunks along S
#define Lq (Sq / Cq)     // 128 elements per chunk

// Per-(b,chunk,h) chunk aggregates of omega*delta. 2 MB -> L2-resident.
__device__ __align__(16) float g_part[(size_t)Bq * Cq * Hq];

typedef unsigned long long u64;

__device__ __forceinline__ u64 pack2(float lo, float hi) {
    u64 r; asm("mov.b64 %0, {%1, %2};" : "=l"(r) : "f"(lo), "f"(hi)); return r;
}
__device__ __forceinline__ void unpack2(u64 v, float& lo, float& hi) {
    asm("mov.b64 {%0, %1}, %2;" : "=f"(lo), "=f"(hi) : "l"(v));
}
__device__ __forceinline__ u64 fma2(u64 a, u64 b, u64 c) {
    u64 d; asm("fma.rn.f32x2 %0, %1, %2, %3;" : "=l"(d) : "l"(a), "l"(b), "l"(c)); return d;
}
__device__ __forceinline__ u64 add2(u64 a, u64 b) {
    u64 d; asm("add.rn.f32x2 %0, %1, %2;" : "=l"(d) : "l"(a), "l"(b)); return d;
}

#define MAGIC 12582912.0f   // 1.5*2^23: (u+MAGIC)-MAGIC == rint(u) for |u| < 2^22

// ---------------- Phase 1: chunk aggregates via separability ----------------
// agg(b,c,h) = om*2pi*( we2*Sum(x) + L*be2 - Sum_s rint(u_s) ), u_s = x_s*we2 + be2
// Block = 128 threads = 2 chunk-groups of 64 threads (one h each).
__global__ void __launch_bounds__(128) k_partials(const float* __restrict__ x,
                                                  const float* __restrict__ W_e,
                                                  const float* __restrict__ b_e,
                                                  const float* __restrict__ omega) {
    __shared__ float2 shx[2][Lq / 2];
    __shared__ float  s_red[4];
    const int t   = threadIdx.x;
    const int g   = t >> 6;             // chunk group 0..1
    const int h   = t & 63;
    const int bc  = blockIdx.x * 2 + g; // b*Cq + c
    const int b   = bc >> 5;

    const float2* xc = (const float2*)(x + (size_t)b * Sq + (size_t)(bc & 31) * Lq);
    float2 v = __ldg(xc + h);
    shx[g][h] = v;

    const float INV_2PI = 0.15915494309189535f;
    const float TWO_PI  = 6.283185307179586f;
    const float we2 = W_e[h]   * INV_2PI;
    const float be2 = b_e[h]   * INV_2PI;
    const float om2 = omega[h] * TWO_PI;

    // Cooperative Sum(x) over the chunk (2 warps per group -> smem combine).
    float ps = v.x + v.y;
#pragma unroll
    for (int o = 16; o > 0; o >>= 1) ps += __shfl_down_sync(0xffffffffu, ps, o);
    if ((t & 31) == 0) s_red[t >> 5] = ps;
    __syncthreads();
    const float sx = s_red[2 * g] + s_red[2 * g + 1];

    // Sum of rint(u_s), packed 2 s-elements per instruction.
    const u64 we2p  = pack2(we2, we2);
    const u64 be2p  = pack2(be2, be2);
    const u64 Mp    = pack2(MAGIC, MAGIC);
    const u64 negMp = pack2(-MAGIC, -MAGIC);
    u64 racc2 = 0ull;
#pragma unroll 16
    for (int i = 0; i < Lq / 2; ++i) {
        float2 xv = shx[g][i];
        u64 u2 = fma2(pack2(xv.x, xv.y), we2p, be2p);
        u64 k2 = add2(add2(u2, Mp), negMp);   // exact rint values
        racc2 = add2(racc2, k2);
    }
    float rlo, rhi; unpack2(racc2, rlo, rhi);
    g_part[(size_t)bc * Hq + h] = om2 * (fmaf(we2, sx, (float)Lq * be2) - (rlo + rhi));
}

// ---------------- Phase 2: fused prefix + scan + output head ----------------
// Block = 64 threads = 2 warps; each warp owns one chunk; lane l owns h = 2l, 2l+1.
__global__ void __launch_bounds__(Hq) k_scan(const float* __restrict__ x,
                                             const float* __restrict__ W_e,
                                             const float* __restrict__ b_e,
                                             const float* __restrict__ omega,
                                             const float* __restrict__ W_r,
                                             const float* __restrict__ b_r,
                                             float* __restrict__ out,
                                             float* __restrict__ hseq) {
    __shared__ float2 shx[2][Lq];       // x duplicated {x,x} per chunk
    const int t   = threadIdx.x;
    const int g   = t >> 5;             // warp = chunk group 0..1
    const int l   = t & 31;
    const int bc0 = blockIdx.x * 2;
    const int b   = bc0 >> 5;
    const int c0  = bc0 & 31;
    const int c   = c0 + g;
    const int h0  = 2 * l;

    // Stage 2 chunks (256 floats), duplicated for LDS.64 broadcast.
    const float4* xg = (const float4*)(x + (size_t)b * Sq + (size_t)c0 * Lq);
    {
        float4 v = __ldg(xg + t);       // t = 0..63 covers 256 floats
        int base = 4 * t;
        shx[base >> 7][(base >> 0 & 127) + 0] = make_float2(v.x, v.x);
        shx[base >> 7][(base      & 127) + 1] = make_float2(v.y, v.y);
        shx[base >> 7][(base      & 127) + 2] = make_float2(v.z, v.z);
        shx[base >> 7][(base      & 127) + 3] = make_float2(v.w, v.w);
    }

    const float INV_2PI = 0.15915494309189535f;
    const float TWO_PI  = 6.283185307179586f;
    const u64 we2p = pack2(W_e[h0]   * INV_2PI, W_e[h0 + 1]   * INV_2PI);
    const u64 be2p = pack2(b_e[h0]   * INV_2PI, b_e[h0 + 1]   * INV_2PI);
    const u64 om2p = pack2(omega[h0] * TWO_PI,  omega[h0 + 1] * TWO_PI);
    const u64 Mp    = pack2(MAGIC, MAGIC);
    const u64 negMp = pack2(-MAGIC, -MAGIC);
    const u64 nOne  = pack2(-1.0f, -1.0f);

    // Carry = sum of predecessor chunk aggregates (L2-resident float2 loads).
    float a0 = 0.f, a1 = 0.f;
    const float2* gp = (const float2*)(&g_part[(size_t)(b << 5) * Hq + h0]);
    for (int cc = 0; cc < c; ++cc) {
        float2 v = __ldg(gp + cc * (Hq / 2));
        a0 += v.x; a1 += v.y;
    }
    u64 acc2 = pack2(a0, a1);
    __syncthreads();

    // Carry-seeded scan: 2 channels/lane, STG.64 streaming per step.
    const u64* xs_p = (const u64*)&shx[g][0];
    char* hp = (char*)(hseq + ((size_t)b * Sq + (size_t)c * Lq) * Hq + h0);
#pragma unroll 8
    for (int s = 0; s < Lq; ++s) {
        u64 x2 = xs_p[s];                       // LDS.64 broadcast {x,x}
        u64 u2 = fma2(x2, we2p, be2p);
        u64 k2 = add2(add2(u2, Mp), negMp);     // rint(u) exactly
        u64 f2 = fma2(k2, nOne, u2);            // u - k (exact subtract)
        acc2 = fma2(om2p, f2, acc2);
        __stcs((long long*)(hp + (size_t)s * (Hq * 4)), (long long)acc2);
    }

    // Output head: last chunk's accumulators are ph[b][h0], ph[b][h0+1].
    if (c == Cq - 1) {
        float p0, p1; unpack2(acc2, p0, p1);
        float tval;
        tval = p0 * W_r[2 * Hq + h0];
        tval = fmaf(cosf(p0), W_r[h0], tval);
        tval = fmaf(sinf(p0), W_r[Hq + h0], tval);
        tval = fmaf(p1, W_r[2 * Hq + h0 + 1], tval);
        tval = fmaf(cosf(p1), W_r[h0 + 1], tval);
        tval = fmaf(sinf(p1), W_r[Hq + h0 + 1], tval);
#pragma unroll
        for (int o = 16; o > 0; o >>= 1)
            tval += __shfl_down_sync(0xffffffffu, tval, o);
        if (l == 0) out[b] = tval + b_r[0];
    }
}

extern "C" void kernel_launch(void* const* d_in, const int* in_sizes, int n_in,
                              void* d_out, int out_size) {
    const float* x     = (const float*)d_in[0];
    const float* W_e   = (const float*)d_in[1];
    const float* b_e   = (const float*)d_in[2];
    const float* omega = (const float*)d_in[3];
    const float* W_r   = (const float*)d_in[4];
    const float* b_r   = (const float*)d_in[5];

    float* out  = (float*)d_out;        // out = B floats
    float* hseq = (float*)d_out + Bq;   // then Hseq = B*S*H floats

    k_partials<<<(Bq * Cq) / 2, 128>>>(x, W_e, b_e, omega);
    k_scan<<<(Bq * Cq) / 2, Hq>>>(x, W_e, b_e, omega, W_r, b_r, out, hseq);
}